// round 4
// baseline (speedup 1.0000x reference)
#include <cuda_runtime.h>
#include <math.h>

#define B_  64
#define T_  2048
#define D_  128
#define U_  128
#define G3  384          // 3*U
#define BT  131072       // B*T

// ---------------- scratch (static device buffers; no allocation) ----------------
__device__ float g_W2[D_ * G3];              // sub_kernel_x transposed to (d, n*128+i)
__device__ float g_XK[(size_t)BT * G3];      // x@kernel + bias        (b,t,j)
__device__ float g_XS[(size_t)BT * G3];      // x@sub_kernel_x         (b,t,j)
__device__ float g_SO[(size_t)BT * G3];      // sub_o per step, (t, n, b, o) = FLAT rows
__device__ float g_PO[(size_t)BT * U_];      // sigmoid(flat@agg_w+agg_b), (t, b, u)

// ---------------- W2 transpose: W2[d][n*128+i] = skx[n][d][i] ----------------
__global__ void build_w2_kernel(const float* __restrict__ skx) {
    int idx = blockIdx.x * 256 + threadIdx.x;   // over 3*128*128 = 49152
    if (idx < 3 * 128 * 128) {
        int n = idx / 16384;
        int rem = idx - n * 16384;
        int d = rem >> 7;
        int i = rem & 127;
        g_W2[d * G3 + n * 128 + i] = skx[idx];
    }
}

// ---------------- generic fp32 GEMM: C[M,N] = act(A[M,K] @ W[K,N] + bias) ----------------
// 64x64 tile, 256 threads, 4x4 per thread. K,N multiples of 64. M multiple of 64.
// act: 0 = identity, 1 = sigmoid
__global__ __launch_bounds__(256) void gemm_kernel(
    const float* __restrict__ A, const float* __restrict__ W,
    const float* __restrict__ bias, float* __restrict__ C,
    int K, int N, int act)
{
    __shared__ float Ast[64][68];   // [kk][mm]
    __shared__ float Ws [64][68];   // [kk][nn]

    int m0 = blockIdx.x * 64;
    int n0 = blockIdx.y * 64;
    int t  = threadIdx.x;
    int tx = t & 15;       // 0..15
    int ty = t >> 4;       // 0..15

    float acc[4][4];
#pragma unroll
    for (int r = 0; r < 4; r++)
#pragma unroll
        for (int c = 0; c < 4; c++) acc[r][c] = 0.f;

    for (int k0 = 0; k0 < K; k0 += 64) {
        // load A tile (64 rows x 64 k), store k-major transposed
#pragma unroll
        for (int r = 0; r < 4; r++) {
            int mm = r * 16 + ty;
            float4 v = *reinterpret_cast<const float4*>(&A[(size_t)(m0 + mm) * K + k0 + 4 * tx]);
            Ast[4 * tx + 0][mm] = v.x;
            Ast[4 * tx + 1][mm] = v.y;
            Ast[4 * tx + 2][mm] = v.z;
            Ast[4 * tx + 3][mm] = v.w;
        }
        // load W tile (64 k x 64 n)
#pragma unroll
        for (int r = 0; r < 4; r++) {
            int kk = r * 16 + ty;
            float4 v = *reinterpret_cast<const float4*>(&W[(size_t)(k0 + kk) * N + n0 + 4 * tx]);
            *reinterpret_cast<float4*>(&Ws[kk][4 * tx]) = v;
        }
        __syncthreads();

#pragma unroll
        for (int kk = 0; kk < 64; kk++) {
            float4 av = *reinterpret_cast<const float4*>(&Ast[kk][4 * ty]);
            float4 bv = *reinterpret_cast<const float4*>(&Ws[kk][4 * tx]);
            float a_[4] = {av.x, av.y, av.z, av.w};
            float b_[4] = {bv.x, bv.y, bv.z, bv.w};
#pragma unroll
            for (int r = 0; r < 4; r++)
#pragma unroll
                for (int c = 0; c < 4; c++) acc[r][c] += a_[r] * b_[c];
        }
        __syncthreads();
    }

#pragma unroll
    for (int r = 0; r < 4; r++) {
        float4 v;
        float vv[4];
#pragma unroll
        for (int c = 0; c < 4; c++) {
            float x = acc[r][c];
            if (bias) x += bias[n0 + 4 * tx + c];
            if (act == 1) x = 1.f / (1.f + __expf(-x));
            vv[c] = x;
        }
        v.x = vv[0]; v.y = vv[1]; v.z = vv[2]; v.w = vv[3];
        *reinterpret_cast<float4*>(&C[(size_t)(m0 + 4 * ty + r) * N + n0 + 4 * tx]) = v;
    }
}

// ---------------- Phase A: per-batch s-recurrence (64 CTAs x 384 threads) ----------------
// thread j = n*128 + i. Stage1: agg_in[j] = XS + sum_o s[n,o]*sub_h[n,o,i]
// Stage2 (j = n*128 + o): sub_o = relu(db + sum_i agg_in[n,i]*dense_w[n,i,o]);
//                         s' = rh*sub_o + s*rx; store sub_o to g_SO[t, n, b, o]
#define SMEM_A_FLOATS (49152 + 384 + 384)
__global__ __launch_bounds__(384, 1) void phaseA_kernel(
    const float* __restrict__ subh,   // (3,128,128) [n][o][i]
    const float* __restrict__ densew, // (3,128,128) [n][i][o]
    const float* __restrict__ denseb, // (3,128)
    const float* __restrict__ tkan)   // (3,256)
{
    extern __shared__ float sm[];
    float* dsm  = sm;            // dense_w copy: 49152 floats (192KB)
    float* s_sm = sm + 49152;    // 384
    float* a_sm = s_sm + 384;    // 384

    const int b = blockIdx.x;
    const int j = threadIdx.x;
    const int n = j >> 7;
    const int i = j & 127;

    // cache dense_w in smem
    {
        const float4* src = reinterpret_cast<const float4*>(densew);
        float4* dst = reinterpret_cast<float4*>(dsm);
        for (int p = j; p < 12288; p += 384) dst[p] = src[p];
    }
    // register-resident sub_h column: w[o] = subh[n][o][i]
    float w[128];
#pragma unroll
    for (int o = 0; o < 128; o++) w[o] = __ldg(&subh[(n * 128 + o) * 128 + i]);

    const float rh = tkan[n * 256 + i];
    const float rx = tkan[n * 256 + 128 + i];
    const float db = denseb[j];

    s_sm[j] = 0.f;
    __syncthreads();

    const float* xs_ptr = g_XS + (size_t)b * T_ * G3 + j;
    float*       so_ptr = g_SO + (size_t)n * 8192 + (size_t)b * 128 + i;
    const float* dcol   = dsm + n * 16384 + i;   // dense_w[n][ii][o=i] at dcol[ii*128]

#pragma unroll 1
    for (int t = 0; t < T_; t++) {
        float xs = __ldg(xs_ptr);
        // ---- stage 1 ----
        float acc0 = 0.f, acc1 = 0.f;
        const float4* s4 = reinterpret_cast<const float4*>(s_sm + n * 128);
#pragma unroll
        for (int o4 = 0; o4 < 32; o4 += 2) {
            float4 sa = s4[o4];
            acc0 += sa.x * w[4 * o4 + 0];
            acc1 += sa.y * w[4 * o4 + 1];
            acc0 += sa.z * w[4 * o4 + 2];
            acc1 += sa.w * w[4 * o4 + 3];
            float4 sb = s4[o4 + 1];
            acc0 += sb.x * w[4 * o4 + 4];
            acc1 += sb.y * w[4 * o4 + 5];
            acc0 += sb.z * w[4 * o4 + 6];
            acc1 += sb.w * w[4 * o4 + 7];
        }
        a_sm[j] = xs + acc0 + acc1;
        __syncthreads();

        // ---- stage 2 ----
        float d0 = 0.f, d1 = 0.f;
        const float4* a4 = reinterpret_cast<const float4*>(a_sm + n * 128);
#pragma unroll
        for (int i4 = 0; i4 < 32; i4++) {
            float4 av = a4[i4];
            d0 += av.x * dcol[(4 * i4 + 0) * 128];
            d1 += av.y * dcol[(4 * i4 + 1) * 128];
            d0 += av.z * dcol[(4 * i4 + 2) * 128];
            d1 += av.w * dcol[(4 * i4 + 3) * 128];
        }
        float so = db + d0 + d1;
        so = fmaxf(so, 0.f);
        float snew = rh * so + s_sm[j] * rx;
        *so_ptr = so;
        s_sm[j] = snew;
        __syncthreads();

        xs_ptr += G3;
        so_ptr += 24576;   // 3*64*128 per step
    }
}

// ---------------- Phase C: per-batch h/c recurrence (64 CTAs x 384 threads) ----------------
__global__ __launch_bounds__(384, 1) void phaseC_kernel(
    const float* __restrict__ R,      // (128, 384)
    float* __restrict__ out)          // (B, T, U)
{
    __shared__ float h_sm[128];
    __shared__ float g_sm[384];

    const int b = blockIdx.x;
    const int j = threadIdx.x;

    // register-resident recurrent column: w[k] = R[k][j]
    float w[128];
#pragma unroll
    for (int k = 0; k < 128; k++) w[k] = __ldg(&R[k * G3 + j]);

    float c = 0.f;
    if (j < 128) h_sm[j] = 0.f;
    __syncthreads();

    const float* xk_ptr  = g_XK + (size_t)b * T_ * G3 + j;
    const float* po_ptr  = g_PO + (size_t)b * U_ + j;     // valid only for j<128
    float*       out_ptr = out  + (size_t)b * T_ * U_ + j;

#pragma unroll 1
    for (int t = 0; t < T_; t++) {
        float z  = __ldg(xk_ptr);
        float og = (j < 128) ? __ldg(po_ptr) : 0.f;   // pre-sigmoided o gate

        float acc0 = 0.f, acc1 = 0.f;
        const float4* h4 = reinterpret_cast<const float4*>(h_sm);
#pragma unroll
        for (int k4 = 0; k4 < 32; k4 += 2) {
            float4 ha = h4[k4];
            acc0 += ha.x * w[4 * k4 + 0];
            acc1 += ha.y * w[4 * k4 + 1];
            acc0 += ha.z * w[4 * k4 + 2];
            acc1 += ha.w * w[4 * k4 + 3];
            float4 hb = h4[k4 + 1];
            acc0 += hb.x * w[4 * k4 + 4];
            acc1 += hb.y * w[4 * k4 + 5];
            acc0 += hb.z * w[4 * k4 + 6];
            acc1 += hb.w * w[4 * k4 + 7];
        }
        z += acc0 + acc1;
        g_sm[j] = 1.f / (1.f + __expf(-z));
        __syncthreads();

        if (j < 128) {
            float ig = g_sm[j];
            float fg = g_sm[128 + j];
            float cg = g_sm[256 + j];
            c = fg * c + ig * tanhf(cg);
            float h = og * tanhf(c);
            *out_ptr = h;
            h_sm[j] = h;
        }
        __syncthreads();

        xk_ptr  += G3;
        po_ptr  += 8192;   // 64*128 per step
        out_ptr += U_;
    }
}

// ---------------- launch ----------------
extern "C" void kernel_launch(void* const* d_in, const int* in_sizes, int n_in,
                              void* d_out, int out_size)
{
    (void)in_sizes; (void)n_in; (void)out_size;
    const float* x      = (const float*)d_in[0];   // (64,2048,128)
    const float* kern   = (const float*)d_in[1];   // (128,384)
    const float* reck   = (const float*)d_in[2];   // (128,384)
    const float* bias   = (const float*)d_in[3];   // (384)
    const float* skx    = (const float*)d_in[4];   // (3,128,128)
    const float* skh    = (const float*)d_in[5];   // (3,128,128)
    const float* tkan   = (const float*)d_in[6];   // (3,256)
    const float* dw     = (const float*)d_in[7];   // (3,128,128)
    const float* dbv    = (const float*)d_in[8];   // (3,128)
    const float* aggw   = (const float*)d_in[9];   // (384,128)
    const float* aggb   = (const float*)d_in[10];  // (128)
    float* out = (float*)d_out;

    void *pW2, *pXK, *pXS, *pSO, *pPO;
    cudaGetSymbolAddress(&pW2, g_W2);
    cudaGetSymbolAddress(&pXK, g_XK);
    cudaGetSymbolAddress(&pXS, g_XS);
    cudaGetSymbolAddress(&pSO, g_SO);
    cudaGetSymbolAddress(&pPO, g_PO);

    cudaFuncSetAttribute(phaseA_kernel, cudaFuncAttributeMaxDynamicSharedMemorySize,
                         SMEM_A_FLOATS * (int)sizeof(float));

    // 1) transpose sub_kernel_x -> W2
    build_w2_kernel<<<192, 256>>>(skx);

    // 2) precompute XK = x@kernel + bias ; XS = x@W2
    {
        dim3 grid(BT / 64, G3 / 64);
        gemm_kernel<<<grid, 256>>>(x, kern, bias, (float*)pXK, D_, G3, 0);
        gemm_kernel<<<grid, 256>>>(x, (const float*)pW2, nullptr, (float*)pXS, D_, G3, 0);
    }

    // 3) s-recurrence -> SO
    phaseA_kernel<<<B_, G3, SMEM_A_FLOATS * (int)sizeof(float)>>>(skh, dw, dbv, tkan);

    // 4) PO = sigmoid(FLAT @ agg_w + agg_b)   (FLAT is SO viewed as (T*64, 384))
    {
        dim3 grid(BT / 64, U_ / 64);
        gemm_kernel<<<grid, 256>>>((const float*)pSO, aggw, aggb, (float*)pPO, G3, U_, 1);
    }

    // 5) h/c recurrence -> out
    phaseC_kernel<<<B_, G3>>>(reck, out);
}

// round 5
// speedup vs baseline: 1.0478x; 1.0478x over previous
#include <cuda_runtime.h>
#include <math.h>

#define B_  64
#define T_  2048
#define D_  128
#define U_  128
#define G3  384          // 3*U
#define BT  131072       // B*T

// ---------------- scratch (static device buffers; no allocation) ----------------
__device__ float g_W2[D_ * G3];              // sub_kernel_x transposed to (d, n*128+i)
__device__ float g_XK[(size_t)BT * G3];      // x@kernel + bias        (b,t,j)
__device__ float g_XS[(size_t)BT * G3];      // x@sub_kernel_x         (b,t,j)
__device__ float g_SO[(size_t)BT * G3];      // sub_o per step, (t, n, b, o) = FLAT rows
__device__ float g_PO[(size_t)BT * U_];      // sigmoid(flat@agg_w+agg_b), (t, b, u)

// ---------------- W2 transpose: W2[d][n*128+i] = skx[n][d][i] ----------------
__global__ void build_w2_kernel(const float* __restrict__ skx) {
    int idx = blockIdx.x * 256 + threadIdx.x;   // over 3*128*128 = 49152
    if (idx < 3 * 128 * 128) {
        int n = idx / 16384;
        int rem = idx - n * 16384;
        int d = rem >> 7;
        int i = rem & 127;
        g_W2[d * G3 + n * 128 + i] = skx[idx];
    }
}

// ---------------- fast fp32 GEMM: C[M,N] = act(A[M,K] @ W[K,N] + bias) ----------------
// 128x128 tile, BK=8, 256 threads, 8x8 per thread, double-buffered smem.
// M mult of 128, N mult of 128, K mult of 8. act: 0=identity, 1=sigmoid
__global__ __launch_bounds__(256, 2) void gemm128_kernel(
    const float* __restrict__ A, const float* __restrict__ W,
    const float* __restrict__ bias, float* __restrict__ C,
    int M, int K, int N, int act)
{
    __shared__ float As[2][8][132];   // [buf][k][m], padded
    __shared__ float Bs[2][8][128];   // [buf][k][n]

    const int tid = threadIdx.x;
    const int m0 = blockIdx.x * 128;
    const int n0 = blockIdx.y * 128;

    // A loader: each thread loads float4 along K: row la_m, k-offset la_k
    const int la_m = tid >> 1;
    const int la_k = (tid & 1) * 4;
    // B loader: k row lb_k, 4 cols at lb_n
    const int lb_k = tid >> 5;
    const int lb_n = (tid & 31) * 4;

    const int tx = tid & 15;   // n frag
    const int ty = tid >> 4;   // m frag

    float acc[8][8];
#pragma unroll
    for (int r = 0; r < 8; r++)
#pragma unroll
        for (int c = 0; c < 8; c++) acc[r][c] = 0.f;

    const float* aptr = A + (size_t)(m0 + la_m) * K + la_k;
    const float* bptr = W + (size_t)lb_k * N + n0 + lb_n;

    // prologue: tile 0 -> buf 0
    {
        float4 ga = *reinterpret_cast<const float4*>(aptr);
        float4 gb = *reinterpret_cast<const float4*>(bptr);
        As[0][la_k + 0][la_m] = ga.x;
        As[0][la_k + 1][la_m] = ga.y;
        As[0][la_k + 2][la_m] = ga.z;
        As[0][la_k + 3][la_m] = ga.w;
        *reinterpret_cast<float4*>(&Bs[0][lb_k][lb_n]) = gb;
    }
    __syncthreads();

    const int nkt = K >> 3;
    float4 ga, gb;
#pragma unroll 1
    for (int kt = 0; kt < nkt; kt++) {
        const int cur = kt & 1;
        const int nxt = cur ^ 1;
        if (kt + 1 < nkt) {
            ga = *reinterpret_cast<const float4*>(aptr + (size_t)(kt + 1) * 8);
            gb = *reinterpret_cast<const float4*>(bptr + (size_t)(kt + 1) * 8 * N);
        }
#pragma unroll
        for (int kk = 0; kk < 8; kk++) {
            float4 a0 = *reinterpret_cast<const float4*>(&As[cur][kk][ty * 4]);
            float4 a1 = *reinterpret_cast<const float4*>(&As[cur][kk][64 + ty * 4]);
            float4 b0 = *reinterpret_cast<const float4*>(&Bs[cur][kk][tx * 4]);
            float4 b1 = *reinterpret_cast<const float4*>(&Bs[cur][kk][64 + tx * 4]);
            float am[8] = {a0.x, a0.y, a0.z, a0.w, a1.x, a1.y, a1.z, a1.w};
            float bn[8] = {b0.x, b0.y, b0.z, b0.w, b1.x, b1.y, b1.z, b1.w};
#pragma unroll
            for (int r = 0; r < 8; r++)
#pragma unroll
                for (int c = 0; c < 8; c++)
                    acc[r][c] += am[r] * bn[c];
        }
        if (kt + 1 < nkt) {
            __syncthreads();
            As[nxt][la_k + 0][la_m] = ga.x;
            As[nxt][la_k + 1][la_m] = ga.y;
            As[nxt][la_k + 2][la_m] = ga.z;
            As[nxt][la_k + 3][la_m] = ga.w;
            *reinterpret_cast<float4*>(&Bs[nxt][lb_k][lb_n]) = gb;
            __syncthreads();
        }
    }

    // epilogue
#pragma unroll
    for (int r = 0; r < 8; r++) {
        const int mm = (r < 4) ? (ty * 4 + r) : (64 + ty * 4 + r - 4);
        float out[8];
#pragma unroll
        for (int c = 0; c < 8; c++) {
            const int nn = (c < 4) ? (tx * 4 + c) : (64 + tx * 4 + c - 4);
            float v = acc[r][c];
            if (bias) v += bias[n0 + nn];
            if (act == 1) v = 1.f / (1.f + __expf(-v));
            out[c] = v;
        }
        float* crow = C + (size_t)(m0 + mm) * N + n0;
        *reinterpret_cast<float4*>(&crow[tx * 4])      = make_float4(out[0], out[1], out[2], out[3]);
        *reinterpret_cast<float4*>(&crow[64 + tx * 4]) = make_float4(out[4], out[5], out[6], out[7]);
    }
}

// ---------------- Phase A: per-batch s-recurrence (64 CTAs x 384 threads) ----------------
// thread j = n*128 + i. Stage1: agg_in[j] = XS + sum_o s[n,o]*sub_h[n,o,i]   (sub_h in regs)
// Stage2 (same thread, o=i): sub_o = relu(db + sum_i' agg_in[n,i']*dense_w[n,i',o])
//   dense_w held transposed in smem: dT[n][o*132 + i'] (pad 132 -> conflict-free float4 reads)
#define DT_ROW   132
#define DT_N     (128 * DT_ROW)               // 16896 floats per n
#define SMEM_A_FLOATS (3 * DT_N + 384 + 384)  // 51456 floats = 205,824 B
__global__ __launch_bounds__(384, 1) void phaseA_kernel(
    const float* __restrict__ subh,   // (3,128,128) [n][o][i]
    const float* __restrict__ densew, // (3,128,128) [n][i][o]
    const float* __restrict__ denseb, // (3,128)
    const float* __restrict__ tkan)   // (3,256)
{
    extern __shared__ float sm[];
    float* dsm  = sm;                 // transposed dense_w: 3*16896
    float* s_sm = sm + 3 * DT_N;      // 384
    float* a_sm = s_sm + 384;         // 384

    const int b = blockIdx.x;
    const int j = threadIdx.x;
    const int n = j >> 7;
    const int i = j & 127;

    // transpose dense_w into smem: dT[n][o*132 + i'] = densew[n][i'][o]
    for (int idx = j; idx < 3 * 128 * 128; idx += 384) {
        int nn  = idx >> 14;
        int rem = idx & 16383;
        int ii  = rem >> 7;
        int oo  = rem & 127;
        dsm[nn * DT_N + oo * DT_ROW + ii] = densew[idx];
    }

    // register-resident sub_h column: w[o] = subh[n][o][i]
    float w[128];
#pragma unroll
    for (int o = 0; o < 128; o++) w[o] = __ldg(&subh[(n * 128 + o) * 128 + i]);

    const float rh = tkan[n * 256 + i];
    const float rx = tkan[n * 256 + 128 + i];
    const float db = denseb[j];

    s_sm[j] = 0.f;
    __syncthreads();

    const float* xs_ptr = g_XS + (size_t)b * T_ * G3 + j;
    float*       so_ptr = g_SO + (size_t)n * 8192 + (size_t)b * 128 + i;
    const float* drow   = dsm + n * DT_N + i * DT_ROW;   // this thread's output row (o=i)

#pragma unroll 1
    for (int t = 0; t < T_; t++) {
        float xs = __ldg(xs_ptr);
        // ---- stage 1: agg_in ----
        float acc0 = 0.f, acc1 = 0.f;
        const float4* s4 = reinterpret_cast<const float4*>(s_sm + n * 128);
#pragma unroll
        for (int o4 = 0; o4 < 32; o4 += 2) {
            float4 sa = s4[o4];
            acc0 += sa.x * w[4 * o4 + 0];
            acc1 += sa.y * w[4 * o4 + 1];
            acc0 += sa.z * w[4 * o4 + 2];
            acc1 += sa.w * w[4 * o4 + 3];
            float4 sb = s4[o4 + 1];
            acc0 += sb.x * w[4 * o4 + 4];
            acc1 += sb.y * w[4 * o4 + 5];
            acc0 += sb.z * w[4 * o4 + 6];
            acc1 += sb.w * w[4 * o4 + 7];
        }
        a_sm[j] = xs + acc0 + acc1;
        __syncthreads();

        // ---- stage 2: dense + relu + s update ----
        float d0 = 0.f, d1 = 0.f;
        const float4* a4 = reinterpret_cast<const float4*>(a_sm + n * 128);
#pragma unroll
        for (int i4 = 0; i4 < 32; i4++) {
            float4 av = a4[i4];
            float4 dv = *reinterpret_cast<const float4*>(&drow[4 * i4]);
            d0 += av.x * dv.x;
            d1 += av.y * dv.y;
            d0 += av.z * dv.z;
            d1 += av.w * dv.w;
        }
        float so = db + d0 + d1;
        so = fmaxf(so, 0.f);
        float snew = rh * so + s_sm[j] * rx;
        *so_ptr = so;
        __syncthreads();          // all stage-1 readers of s done before overwrite
        s_sm[j] = snew;
        __syncthreads();

        xs_ptr += G3;
        so_ptr += 24576;   // 3*64*128 per step
    }
}

// ---------------- Phase C: per-batch h/c recurrence (64 CTAs x 384 threads) ----------------
__global__ __launch_bounds__(384, 1) void phaseC_kernel(
    const float* __restrict__ R,      // (128, 384)
    float* __restrict__ out)          // (B, T, U)
{
    __shared__ float h_sm[128];
    __shared__ float g_sm[384];

    const int b = blockIdx.x;
    const int j = threadIdx.x;

    // register-resident recurrent column: w[k] = R[k][j]
    float w[128];
#pragma unroll
    for (int k = 0; k < 128; k++) w[k] = __ldg(&R[k * G3 + j]);

    float c = 0.f;
    if (j < 128) h_sm[j] = 0.f;
    __syncthreads();

    const float* xk_ptr  = g_XK + (size_t)b * T_ * G3 + j;
    const float* po_ptr  = g_PO + (size_t)b * U_ + j;     // valid only for j<128
    float*       out_ptr = out  + (size_t)b * T_ * U_ + j;

#pragma unroll 1
    for (int t = 0; t < T_; t++) {
        float z  = __ldg(xk_ptr);
        float og = (j < 128) ? __ldg(po_ptr) : 0.f;   // pre-sigmoided o gate

        float acc0 = 0.f, acc1 = 0.f;
        const float4* h4 = reinterpret_cast<const float4*>(h_sm);
#pragma unroll
        for (int k4 = 0; k4 < 32; k4 += 2) {
            float4 ha = h4[k4];
            acc0 += ha.x * w[4 * k4 + 0];
            acc1 += ha.y * w[4 * k4 + 1];
            acc0 += ha.z * w[4 * k4 + 2];
            acc1 += ha.w * w[4 * k4 + 3];
            float4 hb = h4[k4 + 1];
            acc0 += hb.x * w[4 * k4 + 4];
            acc1 += hb.y * w[4 * k4 + 5];
            acc0 += hb.z * w[4 * k4 + 6];
            acc1 += hb.w * w[4 * k4 + 7];
        }
        z += acc0 + acc1;
        g_sm[j] = 1.f / (1.f + __expf(-z));
        __syncthreads();

        if (j < 128) {
            float ig = g_sm[j];
            float fg = g_sm[128 + j];
            float cg = g_sm[256 + j];
            c = fg * c + ig * tanhf(cg);
            float h = og * tanhf(c);
            *out_ptr = h;
            h_sm[j] = h;
        }
        __syncthreads();

        xk_ptr  += G3;
        po_ptr  += 8192;   // 64*128 per step
        out_ptr += U_;
    }
}

// ---------------- launch ----------------
extern "C" void kernel_launch(void* const* d_in, const int* in_sizes, int n_in,
                              void* d_out, int out_size)
{
    (void)in_sizes; (void)n_in; (void)out_size;
    const float* x      = (const float*)d_in[0];   // (64,2048,128)
    const float* kern   = (const float*)d_in[1];   // (128,384)
    const float* reck   = (const float*)d_in[2];   // (128,384)
    const float* bias   = (const float*)d_in[3];   // (384)
    const float* skx    = (const float*)d_in[4];   // (3,128,128)
    const float* skh    = (const float*)d_in[5];   // (3,128,128)
    const float* tkan   = (const float*)d_in[6];   // (3,256)
    const float* dw     = (const float*)d_in[7];   // (3,128,128)
    const float* dbv    = (const float*)d_in[8];   // (3,128)
    const float* aggw   = (const float*)d_in[9];   // (384,128)
    const float* aggb   = (const float*)d_in[10];  // (128)
    float* out = (float*)d_out;

    void *pW2, *pXK, *pXS, *pSO, *pPO;
    cudaGetSymbolAddress(&pW2, g_W2);
    cudaGetSymbolAddress(&pXK, g_XK);
    cudaGetSymbolAddress(&pXS, g_XS);
    cudaGetSymbolAddress(&pSO, g_SO);
    cudaGetSymbolAddress(&pPO, g_PO);

    cudaFuncSetAttribute(phaseA_kernel, cudaFuncAttributeMaxDynamicSharedMemorySize,
                         SMEM_A_FLOATS * (int)sizeof(float));

    // 1) transpose sub_kernel_x -> W2
    build_w2_kernel<<<192, 256>>>(skx);

    // 2) precompute XK = x@kernel + bias ; XS = x@W2
    {
        dim3 grid(BT / 128, G3 / 128);
        gemm128_kernel<<<grid, 256>>>(x, kern, bias, (float*)pXK, BT, D_, G3, 0);
        gemm128_kernel<<<grid, 256>>>(x, (const float*)pW2, nullptr, (float*)pXS, BT, D_, G3, 0);
    }

    // 3) s-recurrence -> SO
    phaseA_kernel<<<B_, G3, SMEM_A_FLOATS * (int)sizeof(float)>>>(skh, dw, dbv, tkan);

    // 4) PO = sigmoid(FLAT @ agg_w + agg_b)   (FLAT is SO viewed as (T*64, 384))
    {
        dim3 grid(BT / 128, U_ / 128);
        gemm128_kernel<<<grid, 256>>>((const float*)pSO, aggw, aggb, (float*)pPO, BT, G3, U_, 1);
    }

    // 5) h/c recurrence -> out
    phaseC_kernel<<<B_, G3>>>(reck, out);
}

// round 9
// speedup vs baseline: 1.1055x; 1.0550x over previous
#include <cuda_runtime.h>
#include <math.h>

#define B_  64
#define T_  2048
#define D_  128
#define U_  128
#define G3  384          // 3*U
#define BT  131072       // B*T

typedef unsigned long long ull;

// ---------------- f32x2 helpers (phaseC) ----------------
__device__ __forceinline__ ull pack2(float lo, float hi) {
    ull r; asm("mov.b64 %0, {%1,%2};" : "=l"(r) : "f"(lo), "f"(hi)); return r;
}
__device__ __forceinline__ float hsum2(ull a, ull b) {
    float alo, ahi, blo, bhi;
    asm("mov.b64 {%0,%1}, %2;" : "=f"(alo), "=f"(ahi) : "l"(a));
    asm("mov.b64 {%0,%1}, %2;" : "=f"(blo), "=f"(bhi) : "l"(b));
    return (alo + blo) + (ahi + bhi);
}
__device__ __forceinline__ ull ffma2(ull a, ull b, ull c) {
    ull d; asm("fma.rn.f32x2 %0, %1, %2, %3;" : "=l"(d) : "l"(a), "l"(b), "l"(c)); return d;
}

// ---------------- scratch (static device buffers; no allocation) ----------------
__device__ float g_W2[D_ * G3];              // sub_kernel_x transposed to (d, n*128+i)
__device__ float g_XK[(size_t)BT * G3];      // x@kernel + bias        (b,t,j)
__device__ float g_XS[(size_t)BT * G3];      // x@sub_kernel_x         (b,t,j)
__device__ float g_SO[(size_t)BT * G3];      // sub_o per step, (t, n, b, o) = FLAT rows
__device__ float g_PO[(size_t)BT * U_];      // sigmoid(flat@agg_w+agg_b), (t, b, u)

// ---------------- W2 transpose: W2[d][n*128+i] = skx[n][d][i] ----------------
__global__ void build_w2_kernel(const float* __restrict__ skx) {
    int idx = blockIdx.x * 256 + threadIdx.x;   // over 3*128*128 = 49152
    if (idx < 3 * 128 * 128) {
        int n = idx / 16384;
        int rem = idx - n * 16384;
        int d = rem >> 7;
        int i = rem & 127;
        g_W2[d * G3 + n * 128 + i] = skx[idx];
    }
}

// ---------------- fast fp32 GEMM: C[M,N] = act(A[M,K] @ W[K,N] + bias) ----------------
__global__ __launch_bounds__(256, 2) void gemm128_kernel(
    const float* __restrict__ A, const float* __restrict__ W,
    const float* __restrict__ bias, float* __restrict__ C,
    int M, int K, int N, int act)
{
    __shared__ float As[2][8][132];   // [buf][k][m], padded
    __shared__ float Bs[2][8][128];   // [buf][k][n]

    const int tid = threadIdx.x;
    const int m0 = blockIdx.x * 128;
    const int n0 = blockIdx.y * 128;

    const int la_m = tid >> 1;
    const int la_k = (tid & 1) * 4;
    const int lb_k = tid >> 5;
    const int lb_n = (tid & 31) * 4;

    const int tx = tid & 15;
    const int ty = tid >> 4;

    float acc[8][8];
#pragma unroll
    for (int r = 0; r < 8; r++)
#pragma unroll
        for (int c = 0; c < 8; c++) acc[r][c] = 0.f;

    const float* aptr = A + (size_t)(m0 + la_m) * K + la_k;
    const float* bptr = W + (size_t)lb_k * N + n0 + lb_n;

    {
        float4 ga = *reinterpret_cast<const float4*>(aptr);
        float4 gb = *reinterpret_cast<const float4*>(bptr);
        As[0][la_k + 0][la_m] = ga.x;
        As[0][la_k + 1][la_m] = ga.y;
        As[0][la_k + 2][la_m] = ga.z;
        As[0][la_k + 3][la_m] = ga.w;
        *reinterpret_cast<float4*>(&Bs[0][lb_k][lb_n]) = gb;
    }
    __syncthreads();

    const int nkt = K >> 3;
    float4 ga, gb;
#pragma unroll 1
    for (int kt = 0; kt < nkt; kt++) {
        const int cur = kt & 1;
        const int nxt = cur ^ 1;
        if (kt + 1 < nkt) {
            ga = *reinterpret_cast<const float4*>(aptr + (size_t)(kt + 1) * 8);
            gb = *reinterpret_cast<const float4*>(bptr + (size_t)(kt + 1) * 8 * N);
        }
#pragma unroll
        for (int kk = 0; kk < 8; kk++) {
            float4 a0 = *reinterpret_cast<const float4*>(&As[cur][kk][ty * 4]);
            float4 a1 = *reinterpret_cast<const float4*>(&As[cur][kk][64 + ty * 4]);
            float4 b0 = *reinterpret_cast<const float4*>(&Bs[cur][kk][tx * 4]);
            float4 b1 = *reinterpret_cast<const float4*>(&Bs[cur][kk][64 + tx * 4]);
            float am[8] = {a0.x, a0.y, a0.z, a0.w, a1.x, a1.y, a1.z, a1.w};
            float bn[8] = {b0.x, b0.y, b0.z, b0.w, b1.x, b1.y, b1.z, b1.w};
#pragma unroll
            for (int r = 0; r < 8; r++)
#pragma unroll
                for (int c = 0; c < 8; c++)
                    acc[r][c] += am[r] * bn[c];
        }
        if (kt + 1 < nkt) {
            __syncthreads();
            As[nxt][la_k + 0][la_m] = ga.x;
            As[nxt][la_k + 1][la_m] = ga.y;
            As[nxt][la_k + 2][la_m] = ga.z;
            As[nxt][la_k + 3][la_m] = ga.w;
            *reinterpret_cast<float4*>(&Bs[nxt][lb_k][lb_n]) = gb;
            __syncthreads();
        }
    }

#pragma unroll
    for (int r = 0; r < 8; r++) {
        const int mm = (r < 4) ? (ty * 4 + r) : (64 + ty * 4 + r - 4);
        float out[8];
#pragma unroll
        for (int c = 0; c < 8; c++) {
            const int nn = (c < 4) ? (tx * 4 + c) : (64 + tx * 4 + c - 4);
            float v = acc[r][c];
            if (bias) v += bias[n0 + nn];
            if (act == 1) v = 1.f / (1.f + __expf(-v));
            out[c] = v;
        }
        float* crow = C + (size_t)(m0 + mm) * N + n0;
        *reinterpret_cast<float4*>(&crow[tx * 4])      = make_float4(out[0], out[1], out[2], out[3]);
        *reinterpret_cast<float4*>(&crow[64 + tx * 4]) = make_float4(out[4], out[5], out[6], out[7]);
    }
}

// ---------------- Phase A: per-batch s-recurrence (64 CTAs x 384 threads) ----------------
// R4-proven scalar arithmetic; s ping-pong (2 barriers/step) + xs prefetch.
#define DT_ROW   132
#define DT_N     (128 * DT_ROW)               // 16896 floats per n
#define SA_OFF   (3 * DT_N)                   // s ping-pong: 2 x 384
#define AA_OFF   (SA_OFF + 768)               // agg: 384
#define SMEM_A_FLOATS (AA_OFF + 384)          // 51840 floats = 207,360 B
__global__ __launch_bounds__(384, 1) void phaseA_kernel(
    const float* __restrict__ subh,   // (3,128,128) [n][o][i]
    const float* __restrict__ densew, // (3,128,128) [n][i][o]
    const float* __restrict__ denseb, // (3,128)
    const float* __restrict__ tkan)   // (3,256)
{
    extern __shared__ float sm[];
    float* dsm  = sm;                 // transposed dense_w: 3*16896
    float* s_sm = sm + SA_OFF;        // ping-pong [2][384]
    float* a_sm = sm + AA_OFF;        // 384

    const int b = blockIdx.x;
    const int j = threadIdx.x;
    const int n = j >> 7;
    const int i = j & 127;

    // transpose dense_w into smem: dT[n][o*132 + i'] = densew[n][i'][o]
    for (int idx = j; idx < 3 * 128 * 128; idx += 384) {
        int nn  = idx >> 14;
        int rem = idx & 16383;
        int ii  = rem >> 7;
        int oo  = rem & 127;
        dsm[nn * DT_N + oo * DT_ROW + ii] = densew[idx];
    }

    // register-resident sub_h column: w[o] = subh[n][o][i]
    float w[128];
#pragma unroll
    for (int o = 0; o < 128; o++) w[o] = __ldg(&subh[(n * 128 + o) * 128 + i]);

    const float rh = tkan[n * 256 + i];
    const float rx = tkan[n * 256 + 128 + i];
    const float db = denseb[j];

    s_sm[j] = 0.f;                    // buffer 0
    __syncthreads();

    const float* xs_ptr = g_XS + (size_t)b * T_ * G3 + j;
    float*       so_ptr = g_SO + (size_t)n * 8192 + (size_t)b * 128 + i;
    const float* drow   = dsm + n * DT_N + i * DT_ROW;   // this thread's output row (o=i)

    float xs = __ldg(xs_ptr);
    xs_ptr += G3;

#pragma unroll 1
    for (int t = 0; t < T_; t++) {
        float nx = 0.f;
        if (t + 1 < T_) nx = __ldg(xs_ptr);

        const float* scur = s_sm + (t & 1) * 384;
        float*       snxt = s_sm + ((t & 1) ^ 1) * 384;

        // ---- stage 1: agg_in ----
        float acc0 = 0.f, acc1 = 0.f;
        const float4* s4 = reinterpret_cast<const float4*>(scur + n * 128);
#pragma unroll
        for (int o4 = 0; o4 < 32; o4 += 2) {
            float4 sa = s4[o4];
            acc0 += sa.x * w[4 * o4 + 0];
            acc1 += sa.y * w[4 * o4 + 1];
            acc0 += sa.z * w[4 * o4 + 2];
            acc1 += sa.w * w[4 * o4 + 3];
            float4 sb = s4[o4 + 1];
            acc0 += sb.x * w[4 * o4 + 4];
            acc1 += sb.y * w[4 * o4 + 5];
            acc0 += sb.z * w[4 * o4 + 6];
            acc1 += sb.w * w[4 * o4 + 7];
        }
        a_sm[j] = xs + acc0 + acc1;
        __syncthreads();

        // ---- stage 2: dense + relu + s update ----
        float d0 = 0.f, d1 = 0.f;
        const float4* a4 = reinterpret_cast<const float4*>(a_sm + n * 128);
#pragma unroll
        for (int i4 = 0; i4 < 32; i4++) {
            float4 av = a4[i4];
            float4 dv = *reinterpret_cast<const float4*>(&drow[4 * i4]);
            d0 += av.x * dv.x;
            d1 += av.y * dv.y;
            d0 += av.z * dv.z;
            d1 += av.w * dv.w;
        }
        float so = db + d0 + d1;
        so = fmaxf(so, 0.f);
        float snew = rh * so + scur[j] * rx;
        *so_ptr = so;
        snxt[j] = snew;
        __syncthreads();

        xs = nx;
        xs_ptr += G3;
        so_ptr += 24576;   // 3*64*128 per step
    }
}

// ---------------- Phase C: per-batch h/c recurrence (64 CTAs x 384 threads) ----------------
// f32x2 packed FMAs, FIXED: full 128-wide k range (wc[64], q<32).
__global__ __launch_bounds__(384, 1) void phaseC_kernel(
    const float* __restrict__ R,      // (128, 384)
    float* __restrict__ out)          // (B, T, U)
{
    __shared__ __align__(16) float h_sm[256];   // ping-pong [2][128]
    __shared__ float g_sm[384];

    const int b = blockIdx.x;
    const int j = threadIdx.x;

    // packed recurrent column: wc[q] = (R[2q][j], R[2q+1][j]), q=0..63 -> k=0..127
    ull wc[64];
#pragma unroll
    for (int q = 0; q < 64; q++) {
        float lo = __ldg(&R[(2 * q) * G3 + j]);
        float hi = __ldg(&R[(2 * q + 1) * G3 + j]);
        wc[q] = pack2(lo, hi);
    }

    float c = 0.f;
    if (j < 128) h_sm[j] = 0.f;
    __syncthreads();

    const float* xk_ptr  = g_XK + (size_t)b * T_ * G3 + j;
    const float* po_ptr  = g_PO + (size_t)b * U_ + j;     // valid only for j<128
    float*       out_ptr = out  + (size_t)b * T_ * U_ + j;

    float z0 = __ldg(xk_ptr);
    float og0 = (j < 128) ? __ldg(po_ptr) : 0.f;
    xk_ptr += G3; po_ptr += 8192;

#pragma unroll 1
    for (int t = 0; t < T_; t++) {
        float nz = 0.f, nog = 0.f;
        if (t + 1 < T_) {
            nz = __ldg(xk_ptr);
            if (j < 128) nog = __ldg(po_ptr);
        }

        const ulonglong2* h22 = reinterpret_cast<const ulonglong2*>(h_sm + (t & 1) * 128);
        ull acc0 = 0, acc1 = 0;
#pragma unroll
        for (int q = 0; q < 32; q++) {
            ulonglong2 hv = h22[q];                 // floats (4q,4q+1) and (4q+2,4q+3)
            acc0 = ffma2(hv.x, wc[2 * q],     acc0);
            acc1 = ffma2(hv.y, wc[2 * q + 1], acc1);
        }
        float z = z0 + hsum2(acc0, acc1);
        g_sm[j] = 1.f / (1.f + __expf(-z));
        __syncthreads();

        if (j < 128) {
            float ig = g_sm[j];
            float fg = g_sm[128 + j];
            float cg = g_sm[256 + j];
            c = fg * c + ig * tanhf(cg);
            float h = og0 * tanhf(c);
            *out_ptr = h;
            h_sm[((t & 1) ^ 1) * 128 + j] = h;
        }
        __syncthreads();

        z0 = nz; og0 = nog;
        xk_ptr += G3; po_ptr += 8192; out_ptr += U_;
    }
}

// ---------------- launch ----------------
extern "C" void kernel_launch(void* const* d_in, const int* in_sizes, int n_in,
                              void* d_out, int out_size)
{
    (void)in_sizes; (void)n_in; (void)out_size;
    const float* x      = (const float*)d_in[0];   // (64,2048,128)
    const float* kern   = (const float*)d_in[1];   // (128,384)
    const float* reck   = (const float*)d_in[2];   // (128,384)
    const float* bias   = (const float*)d_in[3];   // (384)
    const float* skx    = (const float*)d_in[4];   // (3,128,128)
    const float* skh    = (const float*)d_in[5];   // (3,128,128)
    const float* tkan   = (const float*)d_in[6];   // (3,256)
    const float* dw     = (const float*)d_in[7];   // (3,128,128)
    const float* dbv    = (const float*)d_in[8];   // (3,128)
    const float* aggw   = (const float*)d_in[9];   // (384,128)
    const float* aggb   = (const float*)d_in[10];  // (128)
    float* out = (float*)d_out;

    void *pW2, *pXK, *pXS, *pSO, *pPO;
    cudaGetSymbolAddress(&pW2, g_W2);
    cudaGetSymbolAddress(&pXK, g_XK);
    cudaGetSymbolAddress(&pXS, g_XS);
    cudaGetSymbolAddress(&pSO, g_SO);
    cudaGetSymbolAddress(&pPO, g_PO);

    cudaFuncSetAttribute(phaseA_kernel, cudaFuncAttributeMaxDynamicSharedMemorySize,
                         SMEM_A_FLOATS * (int)sizeof(float));

    // side stream + events for overlapping the XK GEMM with the main chain
    static cudaStream_t s2 = nullptr;
    static cudaEvent_t evF = nullptr, evX = nullptr;
    if (s2 == nullptr) {
        cudaStreamCreateWithFlags(&s2, cudaStreamNonBlocking);
        cudaEventCreateWithFlags(&evF, cudaEventDisableTiming);
        cudaEventCreateWithFlags(&evX, cudaEventDisableTiming);
    }

    // fork: XK = x@kernel + bias on side stream (independent of everything else)
    cudaEventRecord(evF, 0);
    cudaStreamWaitEvent(s2, evF, 0);
    {
        dim3 grid(BT / 128, G3 / 128);
        gemm128_kernel<<<grid, 256, 0, s2>>>(x, kern, bias, (float*)pXK, BT, D_, G3, 0);
    }
    cudaEventRecord(evX, s2);

    // main stream: W2 transpose, XS GEMM, phaseA, PO GEMM
    build_w2_kernel<<<192, 256>>>(skx);
    {
        dim3 grid(BT / 128, G3 / 128);
        gemm128_kernel<<<grid, 256>>>(x, (const float*)pW2, nullptr, (float*)pXS, BT, D_, G3, 0);
    }

    phaseA_kernel<<<B_, G3, SMEM_A_FLOATS * (int)sizeof(float)>>>(skh, dw, dbv, tkan);

    {
        dim3 grid(BT / 128, U_ / 128);
        gemm128_kernel<<<grid, 256>>>((const float*)pSO, aggw, aggb, (float*)pPO, BT, G3, U_, 1);
    }

    // join: phaseC needs XK (side stream) + PO
    cudaStreamWaitEvent(0, evX, 0);
    phaseC_kernel<<<B_, G3>>>(reck, out);
}

// round 11
// speedup vs baseline: 1.4290x; 1.2927x over previous
#include <cuda_runtime.h>
#include <math.h>

#define B_  64
#define T_  2048
#define D_  128
#define U_  128
#define G3  384          // 3*U
#define BT  131072       // B*T

typedef unsigned long long ull;

// ---------------- f32x2 helpers (proven in R9 phaseC) ----------------
__device__ __forceinline__ ull pack2(float lo, float hi) {
    ull r; asm("mov.b64 %0, {%1,%2};" : "=l"(r) : "f"(lo), "f"(hi)); return r;
}
__device__ __forceinline__ float hsum2(ull a, ull b) {
    float alo, ahi, blo, bhi;
    asm("mov.b64 {%0,%1}, %2;" : "=f"(alo), "=f"(ahi) : "l"(a));
    asm("mov.b64 {%0,%1}, %2;" : "=f"(blo), "=f"(bhi) : "l"(b));
    return (alo + blo) + (ahi + bhi);
}
__device__ __forceinline__ ull ffma2(ull a, ull b, ull c) {
    ull d; asm("fma.rn.f32x2 %0, %1, %2, %3;" : "=l"(d) : "l"(a), "l"(b), "l"(c)); return d;
}

// ---------------- scratch (static device buffers; no allocation) ----------------
__device__ float g_W2[D_ * G3];              // sub_kernel_x transposed to (d, n*128+i)
__device__ float g_XK[(size_t)BT * G3];      // x@kernel + bias        (b,t,j)
__device__ float g_XS[(size_t)BT * G3];      // x@sub_kernel_x         (b,t,j)
__device__ float g_SO[(size_t)BT * G3];      // sub_o per step, (t, n, b, o) = FLAT rows
__device__ float g_PO[(size_t)BT * U_];      // sigmoid(flat@agg_w+agg_b), (t, b, u)

// ---------------- W2 transpose: W2[d][n*128+i] = skx[n][d][i] ----------------
__global__ void build_w2_kernel(const float* __restrict__ skx) {
    int idx = blockIdx.x * 256 + threadIdx.x;   // over 3*128*128 = 49152
    if (idx < 3 * 128 * 128) {
        int n = idx / 16384;
        int rem = idx - n * 16384;
        int d = rem >> 7;
        int i = rem & 127;
        g_W2[d * G3 + n * 128 + i] = skx[idx];
    }
}

// ---------------- fast fp32 GEMM: C[M,N] = act(A[M,K] @ W[K,N] + bias) ----------------
__global__ __launch_bounds__(256, 2) void gemm128_kernel(
    const float* __restrict__ A, const float* __restrict__ W,
    const float* __restrict__ bias, float* __restrict__ C,
    int M, int K, int N, int act)
{
    __shared__ float As[2][8][132];   // [buf][k][m], padded
    __shared__ float Bs[2][8][128];   // [buf][k][n]

    const int tid = threadIdx.x;
    const int m0 = blockIdx.x * 128;
    const int n0 = blockIdx.y * 128;

    const int la_m = tid >> 1;
    const int la_k = (tid & 1) * 4;
    const int lb_k = tid >> 5;
    const int lb_n = (tid & 31) * 4;

    const int tx = tid & 15;
    const int ty = tid >> 4;

    float acc[8][8];
#pragma unroll
    for (int r = 0; r < 8; r++)
#pragma unroll
        for (int c = 0; c < 8; c++) acc[r][c] = 0.f;

    const float* aptr = A + (size_t)(m0 + la_m) * K + la_k;
    const float* bptr = W + (size_t)lb_k * N + n0 + lb_n;

    {
        float4 ga = *reinterpret_cast<const float4*>(aptr);
        float4 gb = *reinterpret_cast<const float4*>(bptr);
        As[0][la_k + 0][la_m] = ga.x;
        As[0][la_k + 1][la_m] = ga.y;
        As[0][la_k + 2][la_m] = ga.z;
        As[0][la_k + 3][la_m] = ga.w;
        *reinterpret_cast<float4*>(&Bs[0][lb_k][lb_n]) = gb;
    }
    __syncthreads();

    const int nkt = K >> 3;
    float4 ga, gb;
#pragma unroll 1
    for (int kt = 0; kt < nkt; kt++) {
        const int cur = kt & 1;
        const int nxt = cur ^ 1;
        if (kt + 1 < nkt) {
            ga = *reinterpret_cast<const float4*>(aptr + (size_t)(kt + 1) * 8);
            gb = *reinterpret_cast<const float4*>(bptr + (size_t)(kt + 1) * 8 * N);
        }
#pragma unroll
        for (int kk = 0; kk < 8; kk++) {
            float4 a0 = *reinterpret_cast<const float4*>(&As[cur][kk][ty * 4]);
            float4 a1 = *reinterpret_cast<const float4*>(&As[cur][kk][64 + ty * 4]);
            float4 b0 = *reinterpret_cast<const float4*>(&Bs[cur][kk][tx * 4]);
            float4 b1 = *reinterpret_cast<const float4*>(&Bs[cur][kk][64 + tx * 4]);
            float am[8] = {a0.x, a0.y, a0.z, a0.w, a1.x, a1.y, a1.z, a1.w};
            float bn[8] = {b0.x, b0.y, b0.z, b0.w, b1.x, b1.y, b1.z, b1.w};
#pragma unroll
            for (int r = 0; r < 8; r++)
#pragma unroll
                for (int c = 0; c < 8; c++)
                    acc[r][c] += am[r] * bn[c];
        }
        if (kt + 1 < nkt) {
            __syncthreads();
            As[nxt][la_k + 0][la_m] = ga.x;
            As[nxt][la_k + 1][la_m] = ga.y;
            As[nxt][la_k + 2][la_m] = ga.z;
            As[nxt][la_k + 3][la_m] = ga.w;
            *reinterpret_cast<float4*>(&Bs[nxt][lb_k][lb_n]) = gb;
            __syncthreads();
        }
    }

#pragma unroll
    for (int r = 0; r < 8; r++) {
        const int mm = (r < 4) ? (ty * 4 + r) : (64 + ty * 4 + r - 4);
        float out[8];
#pragma unroll
        for (int c = 0; c < 8; c++) {
            const int nn = (c < 4) ? (tx * 4 + c) : (64 + tx * 4 + c - 4);
            float v = acc[r][c];
            if (bias) v += bias[n0 + nn];
            if (act == 1) v = 1.f / (1.f + __expf(-v));
            out[c] = v;
        }
        float* crow = C + (size_t)(m0 + mm) * N + n0;
        *reinterpret_cast<float4*>(&crow[tx * 4])      = make_float4(out[0], out[1], out[2], out[3]);
        *reinterpret_cast<float4*>(&crow[64 + tx * 4]) = make_float4(out[4], out[5], out[6], out[7]);
    }
}

// ---------------- Phase A: s-recurrence, one CTA per (n, batch-pair) -----------------
// 96 CTAs x 128 threads. CTA: n = bid/32, batches b0=2*(bid%32), b1=b0+1.
// thread i: stage1 agg_in[b][i] = XS[b] + sum_o s[b][o]*subh[n][o][i]  (subh packed f32x2 regs)
//           stage2 sub_o[b][i] = relu(db + sum_i' agg[b][i']*dT[i][i'])  (dT read once, used 2x)
#define DT_ROW   132
#define DT_N2    (128 * DT_ROW)               // 16896 floats (one n)
#define SA2_OFF  DT_N2                        // s ping-pong: [2][2][128] = 512
#define AA2_OFF  (SA2_OFF + 512)              // agg: [2][128] = 256
#define SMEM_A2_FLOATS (AA2_OFF + 256)        // 17664 floats = 70,656 B
__global__ __launch_bounds__(128, 1) void phaseA_kernel(
    const float* __restrict__ subh,   // (3,128,128) [n][o][i]
    const float* __restrict__ densew, // (3,128,128) [n][i][o]
    const float* __restrict__ denseb, // (3,128)
    const float* __restrict__ tkan)   // (3,256)
{
    extern __shared__ float sm[];
    float* dsm  = sm;                 // dT[o*132 + i'] = densew[n][i'][o]
    float* s_sm = sm + SA2_OFF;       // [pp][batch][128]
    float* a_sm = sm + AA2_OFF;       // [batch][128]

    const int bid = blockIdx.x;
    const int n  = bid >> 5;          // 0..2
    const int b0 = (bid & 31) * 2;    // 0,2,..,62
    const int i  = threadIdx.x;       // 0..127

    // transpose this n's dense_w into smem
    for (int idx = i; idx < 128 * 128; idx += 128) {
        int ii = idx >> 7;
        int oo = idx & 127;
        dsm[oo * DT_ROW + ii] = densew[n * 16384 + idx];
    }

    // packed sub_h column: w2[q] = (subh[n][2q][i], subh[n][2q+1][i])
    ull w2[64];
#pragma unroll
    for (int q = 0; q < 64; q++) {
        float lo = __ldg(&subh[(n * 128 + 2 * q) * 128 + i]);
        float hi = __ldg(&subh[(n * 128 + 2 * q + 1) * 128 + i]);
        w2[q] = pack2(lo, hi);
    }

    const float rh = tkan[n * 256 + i];
    const float rx = tkan[n * 256 + 128 + i];
    const float db = denseb[n * 128 + i];

    s_sm[i] = 0.f;  s_sm[128 + i] = 0.f;     // pp buffer 0, both batches
    __syncthreads();

    const float* xs0p = g_XS + (size_t)b0 * T_ * G3 + n * 128 + i;
    const float* xs1p = xs0p + (size_t)T_ * G3;
    float*       so_p = g_SO + (size_t)n * 8192 + (size_t)b0 * 128 + i;
    const ulonglong2* d22 = reinterpret_cast<const ulonglong2*>(dsm + i * DT_ROW);

    float xs0 = __ldg(xs0p), xs1 = __ldg(xs1p);
    xs0p += G3; xs1p += G3;

#pragma unroll 1
    for (int t = 0; t < T_; t++) {
        float nx0 = 0.f, nx1 = 0.f;
        if (t + 1 < T_) { nx0 = __ldg(xs0p); nx1 = __ldg(xs1p); }

        const float* scur = s_sm + (t & 1) * 256;
        float*       snxt = s_sm + ((t & 1) ^ 1) * 256;

        // ---- stage 1: agg_in for both batches (sum over o) ----
        const ulonglong2* s22_0 = reinterpret_cast<const ulonglong2*>(scur);
        const ulonglong2* s22_1 = reinterpret_cast<const ulonglong2*>(scur + 128);
        ull a00 = 0, a01 = 0, a10 = 0, a11 = 0;
#pragma unroll
        for (int q = 0; q < 32; q++) {
            ulonglong2 sa = s22_0[q];                 // s[b0]: floats 4q..4q+3
            a00 = ffma2(sa.x, w2[2 * q],     a00);
            a01 = ffma2(sa.y, w2[2 * q + 1], a01);
            ulonglong2 sb = s22_1[q];                 // s[b1]
            a10 = ffma2(sb.x, w2[2 * q],     a10);
            a11 = ffma2(sb.y, w2[2 * q + 1], a11);
        }
        a_sm[i]       = xs0 + hsum2(a00, a01);
        a_sm[128 + i] = xs1 + hsum2(a10, a11);
        __syncthreads();

        // ---- stage 2: dense + relu + s update (dT read once, used for both) ----
        const ulonglong2* a22_0 = reinterpret_cast<const ulonglong2*>(a_sm);
        const ulonglong2* a22_1 = reinterpret_cast<const ulonglong2*>(a_sm + 128);
        ull e00 = 0, e01 = 0, e10 = 0, e11 = 0;
#pragma unroll
        for (int q = 0; q < 32; q++) {
            ulonglong2 dv = d22[q];                   // dT[i]: floats 4q..4q+3
            ulonglong2 av0 = a22_0[q];
            e00 = ffma2(av0.x, dv.x, e00);
            e01 = ffma2(av0.y, dv.y, e01);
            ulonglong2 av1 = a22_1[q];
            e10 = ffma2(av1.x, dv.x, e10);
            e11 = ffma2(av1.y, dv.y, e11);
        }
        float so0 = fmaxf(db + hsum2(e00, e01), 0.f);
        float so1 = fmaxf(db + hsum2(e10, e11), 0.f);
        so_p[0]   = so0;
        so_p[128] = so1;
        snxt[i]       = rh * so0 + scur[i] * rx;
        snxt[128 + i] = rh * so1 + scur[128 + i] * rx;
        __syncthreads();

        xs0 = nx0; xs1 = nx1;
        xs0p += G3; xs1p += G3;
        so_p += 24576;   // 3*64*128 per step
    }
}

// ---------------- Phase C: per-batch h/c recurrence (64 CTAs x 384 threads) ----------------
// f32x2 packed FMAs, full 128-wide k range (R9-proven).
__global__ __launch_bounds__(384, 1) void phaseC_kernel(
    const float* __restrict__ R,      // (128, 384)
    float* __restrict__ out)          // (B, T, U)
{
    __shared__ __align__(16) float h_sm[256];   // ping-pong [2][128]
    __shared__ float g_sm[384];

    const int b = blockIdx.x;
    const int j = threadIdx.x;

    // packed recurrent column: wc[q] = (R[2q][j], R[2q+1][j]), q=0..63 -> k=0..127
    ull wc[64];
#pragma unroll
    for (int q = 0; q < 64; q++) {
        float lo = __ldg(&R[(2 * q) * G3 + j]);
        float hi = __ldg(&R[(2 * q + 1) * G3 + j]);
        wc[q] = pack2(lo, hi);
    }

    float c = 0.f;
    if (j < 128) h_sm[j] = 0.f;
    __syncthreads();

    const float* xk_ptr  = g_XK + (size_t)b * T_ * G3 + j;
    const float* po_ptr  = g_PO + (size_t)b * U_ + j;     // valid only for j<128
    float*       out_ptr = out  + (size_t)b * T_ * U_ + j;

    float z0 = __ldg(xk_ptr);
    float og0 = (j < 128) ? __ldg(po_ptr) : 0.f;
    xk_ptr += G3; po_ptr += 8192;

#pragma unroll 1
    for (int t = 0; t < T_; t++) {
        float nz = 0.f, nog = 0.f;
        if (t + 1 < T_) {
            nz = __ldg(xk_ptr);
            if (j < 128) nog = __ldg(po_ptr);
        }

        const ulonglong2* h22 = reinterpret_cast<const ulonglong2*>(h_sm + (t & 1) * 128);
        ull acc0 = 0, acc1 = 0;
#pragma unroll
        for (int q = 0; q < 32; q++) {
            ulonglong2 hv = h22[q];
            acc0 = ffma2(hv.x, wc[2 * q],     acc0);
            acc1 = ffma2(hv.y, wc[2 * q + 1], acc1);
        }
        float z = z0 + hsum2(acc0, acc1);
        g_sm[j] = 1.f / (1.f + __expf(-z));
        __syncthreads();

        if (j < 128) {
            float ig = g_sm[j];
            float fg = g_sm[128 + j];
            float cg = g_sm[256 + j];
            c = fg * c + ig * tanhf(cg);
            float h = og0 * tanhf(c);
            *out_ptr = h;
            h_sm[((t & 1) ^ 1) * 128 + j] = h;
        }
        __syncthreads();

        z0 = nz; og0 = nog;
        xk_ptr += G3; po_ptr += 8192; out_ptr += U_;
    }
}

// ---------------- launch ----------------
extern "C" void kernel_launch(void* const* d_in, const int* in_sizes, int n_in,
                              void* d_out, int out_size)
{
    (void)in_sizes; (void)n_in; (void)out_size;
    const float* x      = (const float*)d_in[0];   // (64,2048,128)
    const float* kern   = (const float*)d_in[1];   // (128,384)
    const float* reck   = (const float*)d_in[2];   // (128,384)
    const float* bias   = (const float*)d_in[3];   // (384)
    const float* skx    = (const float*)d_in[4];   // (3,128,128)
    const float* skh    = (const float*)d_in[5];   // (3,128,128)
    const float* tkan   = (const float*)d_in[6];   // (3,256)
    const float* dw     = (const float*)d_in[7];   // (3,128,128)
    const float* dbv    = (const float*)d_in[8];   // (3,128)
    const float* aggw   = (const float*)d_in[9];   // (384,128)
    const float* aggb   = (const float*)d_in[10];  // (128)
    float* out = (float*)d_out;

    void *pW2, *pXK, *pXS, *pSO, *pPO;
    cudaGetSymbolAddress(&pW2, g_W2);
    cudaGetSymbolAddress(&pXK, g_XK);
    cudaGetSymbolAddress(&pXS, g_XS);
    cudaGetSymbolAddress(&pSO, g_SO);
    cudaGetSymbolAddress(&pPO, g_PO);

    cudaFuncSetAttribute(phaseA_kernel, cudaFuncAttributeMaxDynamicSharedMemorySize,
                         SMEM_A2_FLOATS * (int)sizeof(float));

    // side stream + events for overlapping the XK GEMM with the main chain
    static cudaStream_t s2 = nullptr;
    static cudaEvent_t evF = nullptr, evX = nullptr;
    if (s2 == nullptr) {
        cudaStreamCreateWithFlags(&s2, cudaStreamNonBlocking);
        cudaEventCreateWithFlags(&evF, cudaEventDisableTiming);
        cudaEventCreateWithFlags(&evX, cudaEventDisableTiming);
    }

    // fork: XK = x@kernel + bias on side stream (independent of everything else)
    cudaEventRecord(evF, 0);
    cudaStreamWaitEvent(s2, evF, 0);
    {
        dim3 grid(BT / 128, G3 / 128);
        gemm128_kernel<<<grid, 256, 0, s2>>>(x, kern, bias, (float*)pXK, BT, D_, G3, 0);
    }
    cudaEventRecord(evX, s2);

    // main stream: W2 transpose, XS GEMM, phaseA, PO GEMM
    build_w2_kernel<<<192, 256>>>(skx);
    {
        dim3 grid(BT / 128, G3 / 128);
        gemm128_kernel<<<grid, 256>>>(x, (const float*)pW2, nullptr, (float*)pXS, BT, D_, G3, 0);
    }

    phaseA_kernel<<<96, 128, SMEM_A2_FLOATS * (int)sizeof(float)>>>(skh, dw, dbv, tkan);

    {
        dim3 grid(BT / 128, U_ / 128);
        gemm128_kernel<<<grid, 256>>>((const float*)pSO, aggw, aggb, (float*)pPO, BT, G3, U_, 1);
    }

    // join: phaseC needs XK (side stream) + PO
    cudaStreamWaitEvent(0, evX, 0);
    phaseC_kernel<<<B_, G3>>>(reck, out);
}